// round 13
// baseline (speedup 1.0000x reference)
#include <cuda_runtime.h>
#include <cuda_bf16.h>
#include <cuda_fp16.h>
#include <cstdint>

// Problem constants (fixed by the dataset)
#define NN 4096      // nodes
#define DD 512       // feature dim
#define NW 128       // bitmask words per row (4096/32)

// ---------------- device scratch (no allocation allowed) ----------------
__device__ float    g_angles[NN];
__device__ float    g_acc[NN];
__device__ float    g_a1[NN];
__device__ float    g_a2[NN];
__device__ unsigned g_A [NN * NW];
__device__ unsigned g_A2[NN * NW];
// fp16 split buffers
__device__ __align__(16) __half g_xh[NN * DD];
__device__ __align__(16) __half g_xl[NN * DD];
__device__ __align__(16) __half g_yh[NN * DD];
__device__ __align__(16) __half g_yl[NN * DD];
__device__ __align__(16) __half g_wh[3 * DD * DD];
__device__ __align__(16) __half g_wl[3 * DD * DD];

// ---------------- zero scratch (deterministic per call) ----------------
__global__ void zero_kernel() {
    int idx = blockIdx.x * blockDim.x + threadIdx.x;
    int total = NN * NW;
    for (int i = idx; i < total; i += gridDim.x * blockDim.x) g_A[i] = 0u;
    if (idx < NN) { g_acc[idx] = 0.0f; g_angles[idx] = 0.0f; }
}

// ---------------- fp32 -> (fp16 hi, fp16 lo) split ----------------------
__device__ __forceinline__ void split_store(const float* __restrict__ src,
                                            __half* __restrict__ h,
                                            __half* __restrict__ l, int i)
{
    float4 v = *(const float4*)(src + i);
    __half hx = __float2half_rn(v.x), hy = __float2half_rn(v.y);
    __half hz = __float2half_rn(v.z), hw = __float2half_rn(v.w);
    __half2 h01 = __halves2half2(hx, hy), h23 = __halves2half2(hz, hw);
    __half2 l01 = __halves2half2(__float2half_rn(v.x - __half2float(hx)),
                                 __float2half_rn(v.y - __half2float(hy)));
    __half2 l23 = __halves2half2(__float2half_rn(v.z - __half2float(hz)),
                                 __float2half_rn(v.w - __half2float(hw)));
    *(__half2*)(h + i)     = h01;
    *(__half2*)(h + i + 2) = h23;
    *(__half2*)(l + i)     = l01;
    *(__half2*)(l + i + 2) = l23;
}

__global__ void split_kernel(const float* __restrict__ src,
                             __half* __restrict__ h, __half* __restrict__ l,
                             int n)
{
    int idx = blockIdx.x * blockDim.x + threadIdx.x;
    int i = idx * 4;
    if (i >= n) return;
    split_store(src, h, l, i);
}

// merged 3-weight split (W0, W1, W2 -> g_wh/g_wl slabs)
__global__ void splitw_kernel(const float* __restrict__ W0,
                              const float* __restrict__ W1,
                              const float* __restrict__ W2,
                              __half* __restrict__ h, __half* __restrict__ l)
{
    const int per = DD * DD / 4;
    int idx = blockIdx.x * blockDim.x + threadIdx.x;
    if (idx >= 3 * per) return;
    int arr = idx / per;
    int i = (idx - arr * per) * 4;
    const float* src = arr == 0 ? W0 : (arr == 1 ? W1 : W2);
    split_store(src, h + arr * DD * DD, l + arr * DD * DD, i);
}

// ======================================================================
//  3xFP16 split GEMM, cp.async 5-stage pipeline + ldmatrix + mma.sync:
//     Y = prelu(Xh@Wh^T + Xh@Wl^T + Xl@Wh^T + bias, alpha)
//  MODE 1: store Y as split fp16 pair. MODE 2: fused output head --
//          atomicAdd per-row partials of Y @ Wo^T into g_angles.
//  CTA: 128(M) x 128(N), 512 threads (16 warps 4x4), warp 32x32.
// ======================================================================
#define BM 128
#define BN 128
#define BK 32
#define NT 512
#define LDSH 40                     // padded row stride in halves
#define ARR_B  (128 * LDSH * 2)     // 10240 B per array
#define STAGE_B (4 * ARR_B)         // 40960 B per stage
#define NSTAGE 5
#define GEMM_SMEM (NSTAGE * STAGE_B)   // 204800 B
#define NCH (DD / BK)               // 16

__device__ __forceinline__ void mma_f16_16n8k16(
    float c[4], const uint32_t a[4], const uint32_t b[2])
{
    asm volatile(
        "mma.sync.aligned.m16n8k16.row.col.f32.f16.f16.f32 "
        "{%0,%1,%2,%3}, {%4,%5,%6,%7}, {%8,%9}, {%0,%1,%2,%3};"
        : "+f"(c[0]), "+f"(c[1]), "+f"(c[2]), "+f"(c[3])
        : "r"(a[0]), "r"(a[1]), "r"(a[2]), "r"(a[3]),
          "r"(b[0]), "r"(b[1]));
}

__device__ __forceinline__ void ldsm_x4(uint32_t r[4], uint32_t addr) {
    asm volatile(
        "ldmatrix.sync.aligned.m8n8.x4.shared.b16 {%0,%1,%2,%3}, [%4];"
        : "=r"(r[0]), "=r"(r[1]), "=r"(r[2]), "=r"(r[3]) : "r"(addr));
}

__device__ __forceinline__ void cpa16(uint32_t dst, const void* src) {
    asm volatile("cp.async.cg.shared.global [%0], [%1], 16;"
                 :: "r"(dst), "l"(src) : "memory");
}

template <int MODE>
__global__ __launch_bounds__(NT, 1) void tc_gemm(
    const __half* __restrict__ Xh, const __half* __restrict__ Xl,
    const __half* __restrict__ Wh, const __half* __restrict__ Wl,
    const float* __restrict__ bias, const float* __restrict__ alpha,
    const float* __restrict__ Wo,
    __half* __restrict__ Yh, __half* __restrict__ Yl)
{
    extern __shared__ char sm[];

    const int tid  = threadIdx.x;
    const int lane = tid & 31;
    const int wid  = tid >> 5;          // 0..15
    const int g    = lane >> 2;
    const int t4   = lane & 3;
    const int mwarp = (wid >> 2) * 32;  // 0,32,64,96
    const int nwarp = (wid & 3) * 32;   // 0,32,64,96
    const int bm = blockIdx.y * BM;
    const int bn = blockIdx.x * BN;

    // cp.async mapping: per array, 512 x 16B ops; exactly 1 per thread
    const int crow = tid >> 2;      // 0..127
    const int cq   = tid & 3;       // 16B unit within 64B row chunk

    const int rowA = lane & 15;
    const int kofA = (lane & 16) ? 8 : 0;
    const int rowB = (lane & 7) + ((lane & 16) ? 8 : 0);
    const int kofB = (lane & 8) ? 8 : 0;

    const uint32_t smbase = (uint32_t)__cvta_generic_to_shared(sm);

    float acc[2][4][4];
#pragma unroll
    for (int i = 0; i < 2; ++i)
#pragma unroll
        for (int j = 0; j < 4; ++j)
#pragma unroll
            for (int q = 0; q < 4; ++q) acc[i][j][q] = 0.0f;

    auto issue = [&](int kc) {
        const uint32_t st = smbase + (uint32_t)(kc % NSTAGE) * STAGE_B;
        uint32_t so = (uint32_t)(crow * (LDSH * 2) + cq * 16);
        size_t goA = (size_t)(bm + crow) * DD + kc * BK + cq * 8;
        size_t goB = (size_t)(bn + crow) * DD + kc * BK + cq * 8;
        cpa16(st + 0 * ARR_B + so, Xh + goA);
        cpa16(st + 1 * ARR_B + so, Xl + goA);
        cpa16(st + 2 * ARR_B + so, Wh + goB);
        cpa16(st + 3 * ARR_B + so, Wl + goB);
        asm volatile("cp.async.commit_group;" ::: "memory");
    };

    issue(0); issue(1); issue(2); issue(3);

#pragma unroll 1
    for (int kc = 0; kc < NCH; ++kc) {
        const int rem = NCH - 1 - kc;   // groups we may leave outstanding
        if (rem >= 3)      asm volatile("cp.async.wait_group 3;" ::: "memory");
        else if (rem == 2) asm volatile("cp.async.wait_group 2;" ::: "memory");
        else if (rem == 1) asm volatile("cp.async.wait_group 1;" ::: "memory");
        else               asm volatile("cp.async.wait_group 0;" ::: "memory");
        __syncthreads();
        if (kc + 4 < NCH) issue(kc + 4);

        const uint32_t st  = smbase + (uint32_t)(kc % NSTAGE) * STAGE_B;
        const uint32_t AhU = st;
        const uint32_t AlU = st + ARR_B;
        const uint32_t BhU = st + 2 * ARR_B;
        const uint32_t BlU = st + 3 * ARR_B;

#pragma unroll
        for (int ks = 0; ks < 2; ++ks) {
            uint32_t ah[2][4], al[2][4], bh[4][2], bl[4][2];
            const uint32_t aoff = (uint32_t)(rowA * LDSH + ks * 16 + kofA) * 2u;
            const uint32_t boff = (uint32_t)(rowB * LDSH + ks * 16 + kofB) * 2u;
#pragma unroll
            for (int mt = 0; mt < 2; ++mt) {
                uint32_t mb = (uint32_t)((mwarp + mt * 16) * LDSH) * 2u;
                ldsm_x4(ah[mt], AhU + mb + aoff);
                ldsm_x4(al[mt], AlU + mb + aoff);
            }
#pragma unroll
            for (int p = 0; p < 2; ++p) {
                uint32_t nb = (uint32_t)((nwarp + p * 16) * LDSH) * 2u;
                uint32_t rh[4], rl[4];
                ldsm_x4(rh, BhU + nb + boff);
                ldsm_x4(rl, BlU + nb + boff);
                bh[2 * p][0] = rh[0]; bh[2 * p][1] = rh[1];
                bh[2 * p + 1][0] = rh[2]; bh[2 * p + 1][1] = rh[3];
                bl[2 * p][0] = rl[0]; bl[2 * p][1] = rl[1];
                bl[2 * p + 1][0] = rl[2]; bl[2 * p + 1][1] = rl[3];
            }
#pragma unroll
            for (int mt = 0; mt < 2; ++mt)
#pragma unroll
                for (int nt = 0; nt < 4; ++nt) {
                    mma_f16_16n8k16(acc[mt][nt], ah[mt], bh[nt]);
                    mma_f16_16n8k16(acc[mt][nt], ah[mt], bl[nt]);
                    mma_f16_16n8k16(acc[mt][nt], al[mt], bh[nt]);
                }
        }
    }

    // ---- epilogue ----
    const float alv = alpha[0];
#pragma unroll
    for (int mt = 0; mt < 2; ++mt) {
        int r0 = bm + mwarp + mt * 16 + g;
        float p0 = 0.f, p1 = 0.f;
#pragma unroll
        for (int nt = 0; nt < 4; ++nt) {
            int cb = bn + nwarp + nt * 8 + 2 * t4;
            float b0 = 0.f, b1 = 0.f;
            if (bias) { b0 = bias[cb]; b1 = bias[cb + 1]; }
            float v0 = acc[mt][nt][0] + b0;
            float v1 = acc[mt][nt][1] + b1;
            float v2 = acc[mt][nt][2] + b0;
            float v3 = acc[mt][nt][3] + b1;
            v0 = v0 >= 0.f ? v0 : alv * v0;
            v1 = v1 >= 0.f ? v1 : alv * v1;
            v2 = v2 >= 0.f ? v2 : alv * v2;
            v3 = v3 >= 0.f ? v3 : alv * v3;
            if (MODE == 1) {
                __half h0 = __float2half_rn(v0), h1 = __float2half_rn(v1);
                __half h2 = __float2half_rn(v2), h3 = __float2half_rn(v3);
                __half2 lo01 = __halves2half2(__float2half_rn(v0 - __half2float(h0)),
                                              __float2half_rn(v1 - __half2float(h1)));
                __half2 lo23 = __halves2half2(__float2half_rn(v2 - __half2float(h2)),
                                              __float2half_rn(v3 - __half2float(h3)));
                *(__half2*)&Yh[(size_t)r0 * DD + cb]       = __halves2half2(h0, h1);
                *(__half2*)&Yl[(size_t)r0 * DD + cb]       = lo01;
                *(__half2*)&Yh[(size_t)(r0 + 8) * DD + cb] = __halves2half2(h2, h3);
                *(__half2*)&Yl[(size_t)(r0 + 8) * DD + cb] = lo23;
            } else {
                float w0 = Wo[cb], w1 = Wo[cb + 1];
                p0 = fmaf(v0, w0, fmaf(v1, w1, p0));
                p1 = fmaf(v2, w0, fmaf(v3, w1, p1));
            }
        }
        if (MODE == 2) {
            p0 += __shfl_xor_sync(0xffffffffu, p0, 1);
            p0 += __shfl_xor_sync(0xffffffffu, p0, 2);
            p1 += __shfl_xor_sync(0xffffffffu, p1, 1);
            p1 += __shfl_xor_sync(0xffffffffu, p1, 2);
            if (t4 == 0) {
                atomicAdd(&g_angles[r0],     p0);
                atomicAdd(&g_angles[r0 + 8], p1);
            }
        }
    }
}

// ---------------- edge passes ----------------------------------------
// adjacency build only (runs on side stream, overlapped with GEMMs)
__global__ void edge_adj_kernel(const int* __restrict__ ei, int E)
{
    int t = blockIdx.x * blockDim.x + threadIdx.x;
    if (t >= E) return;
    int s = ei[t];
    int d = ei[E + t];
    atomicOr(&g_A[s * NW + (d >> 5)], 1u << (d & 31));
}

// hop-1 raw segment sum; angles_full(d) = g_angles[d] + bo
__global__ void edge_sum_kernel(const int* __restrict__ ei, int E,
                                const float* __restrict__ bo)
{
    int t = blockIdx.x * blockDim.x + threadIdx.x;
    if (t >= E) return;
    int s = ei[t];
    int d = ei[E + t];
    atomicAdd(&g_acc[s], g_angles[d] + bo[0]);   // duplicates count
}

__global__ void a1_kernel(const float* __restrict__ bo)
{
    int i = blockIdx.x * blockDim.x + threadIdx.x;
    if (i < NN) g_a1[i] = (g_angles[i] + bo[0]) + 0.25f * g_acc[i];  // (0.5)^2
}

// ======================================================================
//  Hop kernels: prefix-sum neighbor extraction + 8-way unrolled row-OR
//  + coalesced broadcast-masked gather.
// ======================================================================
#define NBR_CAP 4096

template <bool STORE_A2>
__device__ __forceinline__ void hop_body(
    const unsigned* __restrict__ nbrmat,
    const float*    __restrict__ vec,
    float scale, float* __restrict__ dst)
{
    const int i = blockIdx.x;
    const int t = threadIdx.x;  // 0..127

    __shared__ unsigned short s_nbr[NBR_CAP];
    __shared__ int   s_wtot[4];
    __shared__ int   s_deg;
    __shared__ unsigned swords[NW];
    __shared__ float red[NW];

    // --- extract this row's neighbor list (deterministic order) ---
    unsigned mybits = g_A[i * NW + t];
    int cnt = __popc(mybits);
    int incl = cnt;
#pragma unroll
    for (int o = 1; o < 32; o <<= 1) {
        int v = __shfl_up_sync(0xffffffffu, incl, o);
        if ((t & 31) >= o) incl += v;
    }
    if ((t & 31) == 31) s_wtot[t >> 5] = incl;
    __syncthreads();
    int base = incl - cnt;
#pragma unroll
    for (int w = 0; w < 4; ++w)
        if (w < (t >> 5)) base += s_wtot[w];
    int pos = base;
    unsigned bb = mybits;
    while (bb) {
        int b = __ffs(bb) - 1;
        bb &= bb - 1;
        s_nbr[pos++] = (unsigned short)(t * 32 + b);
    }
    if (t == 127) s_deg = base + cnt;
    __syncthreads();
    const int deg = s_deg;

    // --- OR neighbor rows (word t), 8-way ILP ---
    unsigned accw = 0u;
    int j = 0;
    for (; j + 8 <= deg; j += 8) {
        unsigned v0 = nbrmat[s_nbr[j]     * NW + t];
        unsigned v1 = nbrmat[s_nbr[j + 1] * NW + t];
        unsigned v2 = nbrmat[s_nbr[j + 2] * NW + t];
        unsigned v3 = nbrmat[s_nbr[j + 3] * NW + t];
        unsigned v4 = nbrmat[s_nbr[j + 4] * NW + t];
        unsigned v5 = nbrmat[s_nbr[j + 5] * NW + t];
        unsigned v6 = nbrmat[s_nbr[j + 6] * NW + t];
        unsigned v7 = nbrmat[s_nbr[j + 7] * NW + t];
        accw |= ((v0 | v1) | (v2 | v3)) | ((v4 | v5) | (v6 | v7));
    }
    for (; j < deg; ++j) accw |= nbrmat[s_nbr[j] * NW + t];

    if (STORE_A2) g_A2[i * NW + t] = accw;
    swords[t] = accw;
    __syncthreads();

    // --- coalesced masked gather: element k*128+t, warp-uniform word ---
    float p = 0.f;
#pragma unroll 4
    for (int k = 0; k < 32; ++k) {
        int idx = k * 128 + t;
        unsigned wrd = swords[idx >> 5];
        p += vec[idx] * (float)((wrd >> (idx & 31)) & 1u);
    }
    red[t] = p;
    __syncthreads();
#pragma unroll
    for (int s = 64; s; s >>= 1) {
        if (t < s) red[t] += red[t + s];
        __syncthreads();
    }
    if (t == 0) dst[i] = vec[i] + scale * red[0];
}

__global__ __launch_bounds__(128) void hop2_kernel()
{
    hop_body<true>(g_A, g_a1, 1.0f / 9.0f, g_a2);
}

__global__ __launch_bounds__(128) void hop3_kernel(float* __restrict__ out)
{
    hop_body<false>(g_A2, g_a2, 1.0f / 16.0f, out);
}

// ---------------------------- launch ------------------------------------
extern "C" void kernel_launch(void* const* d_in, const int* in_sizes, int n_in,
                              void* d_out, int out_size)
{
    const float* coeffs = (const float*)d_in[0];
    const int*   eidx   = (const int*)  d_in[1];
    const float* W0     = (const float*)d_in[2];
    const float* b0     = (const float*)d_in[3];
    const float* a0     = (const float*)d_in[4];
    const float* W1     = (const float*)d_in[5];
    const float* a1p    = (const float*)d_in[6];
    const float* W2     = (const float*)d_in[7];
    const float* a2p    = (const float*)d_in[8];
    const float* Wo     = (const float*)d_in[9];
    const float* bo     = (const float*)d_in[10];
    float* out = (float*)d_out;

    const int E = in_sizes[1] / 2;

    __half *p_xh, *p_xl, *p_yh, *p_yl, *p_wh, *p_wl;
    cudaGetSymbolAddress((void**)&p_xh, g_xh);
    cudaGetSymbolAddress((void**)&p_xl, g_xl);
    cudaGetSymbolAddress((void**)&p_yh, g_yh);
    cudaGetSymbolAddress((void**)&p_yl, g_yl);
    cudaGetSymbolAddress((void**)&p_wh, g_wh);
    cudaGetSymbolAddress((void**)&p_wl, g_wl);

    cudaFuncSetAttribute(tc_gemm<1>, cudaFuncAttributeMaxDynamicSharedMemorySize, GEMM_SMEM);
    cudaFuncSetAttribute(tc_gemm<2>, cudaFuncAttributeMaxDynamicSharedMemorySize, GEMM_SMEM);

    // one-time side stream + events (infra, not work; every call does the
    // same launches in the same graph shape)
    static cudaStream_t s2 = nullptr;
    static cudaEvent_t evFork = nullptr, evJoin = nullptr;
    if (!s2) {
        cudaStreamCreateWithFlags(&s2, cudaStreamNonBlocking);
        cudaEventCreateWithFlags(&evFork, cudaEventDisableTiming);
        cudaEventCreateWithFlags(&evJoin, cudaEventDisableTiming);
    }

    // 1) zero A bitmatrix + hop-1 accumulator + angles
    zero_kernel<<<1024, 256>>>();

    // fork: adjacency build runs concurrently with splits + GEMM chain
    cudaEventRecord(evFork, 0);
    cudaStreamWaitEvent(s2, evFork, 0);
    edge_adj_kernel<<<(E + 255) / 256, 256, 0, s2>>>(eidx, E);
    cudaEventRecord(evJoin, s2);

    // 2) pre-split coeffs and weights to fp16 hi/lo
    split_kernel<<<(NN * DD / 4 + 255) / 256, 256>>>(coeffs, p_xh, p_xl, NN * DD);
    splitw_kernel<<<(3 * DD * DD / 4 + 255) / 256, 256>>>(W0, W1, W2, p_wh, p_wl);

    // 3) MLP: layers 1-2 split-fp16 GEMM+PReLU; layer 3 fused with output head
    dim3 ggrid(DD / BN, NN / BM);   // (4, 32) = 128 CTAs
    tc_gemm<1><<<ggrid, NT, GEMM_SMEM>>>(p_xh, p_xl, p_wh + 0 * DD * DD, p_wl + 0 * DD * DD,
                                         b0,      a0,  nullptr, p_yh, p_yl);
    tc_gemm<1><<<ggrid, NT, GEMM_SMEM>>>(p_yh, p_yl, p_wh + 1 * DD * DD, p_wl + 1 * DD * DD,
                                         nullptr, a1p, nullptr, p_xh, p_xl);
    tc_gemm<2><<<ggrid, NT, GEMM_SMEM>>>(p_xh, p_xl, p_wh + 2 * DD * DD, p_wl + 2 * DD * DD,
                                         nullptr, a2p, Wo, nullptr, nullptr);

    // 4) hop-1 raw segment sum (needs angles) + a1
    edge_sum_kernel<<<(E + 255) / 256, 256>>>(eidx, E, bo);
    a1_kernel<<<(NN + 255) / 256, 256>>>(bo);

    // join: hop2 needs the adjacency bits
    cudaStreamWaitEvent(0, evJoin, 0);

    // 5) hop 2 (materializes A2 bits) and hop 3 (fused, writes output)
    hop2_kernel<<<NN, 128>>>();
    hop3_kernel<<<NN, 128>>>(out);
}

// round 14
// speedup vs baseline: 1.0005x; 1.0005x over previous
#include <cuda_runtime.h>
#include <cuda_bf16.h>
#include <cuda_fp16.h>
#include <cstdint>

// Problem constants (fixed by the dataset)
#define NN 4096      // nodes
#define DD 512       // feature dim
#define NW 128       // bitmask words per row (4096/32)

// ---------------- device scratch (no allocation allowed) ----------------
__device__ float    g_angles[NN];
__device__ float    g_acc[NN];
__device__ float    g_a1[NN];
__device__ float    g_a2[NN];
__device__ unsigned g_A [NN * NW];
__device__ unsigned g_A2[NN * NW];
// fp16 split buffers
__device__ __align__(16) __half g_xh[NN * DD];
__device__ __align__(16) __half g_xl[NN * DD];
__device__ __align__(16) __half g_yh[NN * DD];
__device__ __align__(16) __half g_yl[NN * DD];
__device__ __align__(16) __half g_wh[3 * DD * DD];
__device__ __align__(16) __half g_wl[3 * DD * DD];

// ---------------- zero scratch (deterministic per call) ----------------
__global__ void zero_kernel() {
    int idx = blockIdx.x * blockDim.x + threadIdx.x;
    int total = NN * NW;
    for (int i = idx; i < total; i += gridDim.x * blockDim.x) g_A[i] = 0u;
    if (idx < NN) { g_acc[idx] = 0.0f; g_angles[idx] = 0.0f; }
}

// ---------------- fp32 -> (fp16 hi, fp16 lo) split ----------------------
__device__ __forceinline__ void split_store(const float* __restrict__ src,
                                            __half* __restrict__ h,
                                            __half* __restrict__ l, int i)
{
    float4 v = *(const float4*)(src + i);
    __half hx = __float2half_rn(v.x), hy = __float2half_rn(v.y);
    __half hz = __float2half_rn(v.z), hw = __float2half_rn(v.w);
    __half2 h01 = __halves2half2(hx, hy), h23 = __halves2half2(hz, hw);
    __half2 l01 = __halves2half2(__float2half_rn(v.x - __half2float(hx)),
                                 __float2half_rn(v.y - __half2float(hy)));
    __half2 l23 = __halves2half2(__float2half_rn(v.z - __half2float(hz)),
                                 __float2half_rn(v.w - __half2float(hw)));
    *(__half2*)(h + i)     = h01;
    *(__half2*)(h + i + 2) = h23;
    *(__half2*)(l + i)     = l01;
    *(__half2*)(l + i + 2) = l23;
}

__global__ void split_kernel(const float* __restrict__ src,
                             __half* __restrict__ h, __half* __restrict__ l,
                             int n)
{
    int idx = blockIdx.x * blockDim.x + threadIdx.x;
    int i = idx * 4;
    if (i >= n) return;
    split_store(src, h, l, i);
}

// merged 3-weight split (W0, W1, W2 -> g_wh/g_wl slabs)
__global__ void splitw_kernel(const float* __restrict__ W0,
                              const float* __restrict__ W1,
                              const float* __restrict__ W2,
                              __half* __restrict__ h, __half* __restrict__ l)
{
    const int per = DD * DD / 4;
    int idx = blockIdx.x * blockDim.x + threadIdx.x;
    if (idx >= 3 * per) return;
    int arr = idx / per;
    int i = (idx - arr * per) * 4;
    const float* src = arr == 0 ? W0 : (arr == 1 ? W1 : W2);
    split_store(src, h + arr * DD * DD, l + arr * DD * DD, i);
}

// ======================================================================
//  3xFP16 split GEMM: LDG->reg->STS double-buffered mainloop (proven R8
//  structure, single barrier per chunk), ldmatrix fragments, mma.sync.
//     Y = prelu(Xh@Wh^T + Xh@Wl^T + Xl@Wh^T + bias, alpha)
//  MODE 1: store Y as split fp16 pair. MODE 2: fused output head --
//          atomicAdd per-row partials of Y @ Wo^T into g_angles.
//  CTA: 128(M) x 128(N), 256 threads (8 warps 2x4), warp 64x32.
// ======================================================================
#define BM 128
#define BN 128
#define BK 32
#define NT 256
#define LDSH 40                     // padded row stride in halves
#define ARR_B  (128 * LDSH * 2)     // 10240 B per array
#define STAGE_B (4 * ARR_B)         // 40960 B per stage
#define GEMM_SMEM (2 * STAGE_B)     // 81920 B (double buffer)
#define NCH (DD / BK)               // 16

__device__ __forceinline__ void mma_f16_16n8k16(
    float c[4], const uint32_t a[4], const uint32_t b[2])
{
    asm volatile(
        "mma.sync.aligned.m16n8k16.row.col.f32.f16.f16.f32 "
        "{%0,%1,%2,%3}, {%4,%5,%6,%7}, {%8,%9}, {%0,%1,%2,%3};"
        : "+f"(c[0]), "+f"(c[1]), "+f"(c[2]), "+f"(c[3])
        : "r"(a[0]), "r"(a[1]), "r"(a[2]), "r"(a[3]),
          "r"(b[0]), "r"(b[1]));
}

__device__ __forceinline__ void ldsm_x4(uint32_t r[4], uint32_t addr) {
    asm volatile(
        "ldmatrix.sync.aligned.m8n8.x4.shared.b16 {%0,%1,%2,%3}, [%4];"
        : "=r"(r[0]), "=r"(r[1]), "=r"(r[2]), "=r"(r[3]) : "r"(addr));
}

template <int MODE>
__global__ __launch_bounds__(NT, 1) void tc_gemm(
    const __half* __restrict__ Xh, const __half* __restrict__ Xl,
    const __half* __restrict__ Wh, const __half* __restrict__ Wl,
    const float* __restrict__ bias, const float* __restrict__ alpha,
    const float* __restrict__ Wo,
    __half* __restrict__ Yh, __half* __restrict__ Yl)
{
    extern __shared__ __half sm[];

    const int tid  = threadIdx.x;
    const int lane = tid & 31;
    const int wid  = tid >> 5;          // 0..7
    const int g    = lane >> 2;
    const int t4   = lane & 3;
    const int mwarp = (wid >> 2) * 64;  // 0 or 64
    const int nwarp = (wid & 3) * 32;   // 0..96
    const int bm = blockIdx.y * BM;
    const int bn = blockIdx.x * BN;

    // staging mapping: per array 512 x 16B units; thread does rows crow, crow+64
    const int crow = tid >> 2;      // 0..63
    const int cq   = tid & 3;       // 16B unit within 64B row chunk

    // ldmatrix per-lane offsets (halves)
    const int rowA = lane & 15;
    const int kofA = (lane & 16) ? 8 : 0;
    const int rowB = (lane & 7) + ((lane & 16) ? 8 : 0);
    const int kofB = (lane & 8) ? 8 : 0;

    const uint32_t smbase = (uint32_t)__cvta_generic_to_shared(sm);

    float acc[4][4][4];
#pragma unroll
    for (int i = 0; i < 4; ++i)
#pragma unroll
        for (int j = 0; j < 4; ++j)
#pragma unroll
            for (int q = 0; q < 4; ++q) acc[i][j][q] = 0.0f;

    // prefetch registers: 8 x 16B
    uint4 pah[2], pal[2], pbh[2], pbl[2];
    {
        const int off = cq * 8;
#pragma unroll
        for (int i = 0; i < 2; ++i) {
            int r = crow + i * 64;
            pah[i] = *(const uint4*)(Xh + (size_t)(bm + r) * DD + off);
            pal[i] = *(const uint4*)(Xl + (size_t)(bm + r) * DD + off);
            pbh[i] = *(const uint4*)(Wh + (size_t)(bn + r) * DD + off);
            pbl[i] = *(const uint4*)(Wl + (size_t)(bn + r) * DD + off);
        }
    }

    for (int kc = 0; kc < NCH; ++kc) {
        __half* Ah = sm + (kc & 1) * (STAGE_B / 2);
        __half* Al = Ah + ARR_B / 2;
        __half* Bh = Al + ARR_B / 2;
        __half* Bl = Bh + ARR_B / 2;

        // ---- store prefetched chunk ----
#pragma unroll
        for (int i = 0; i < 2; ++i) {
            int r = crow + i * 64;
            int so = r * LDSH + cq * 8;
            *(uint4*)(Ah + so) = pah[i];
            *(uint4*)(Al + so) = pal[i];
            *(uint4*)(Bh + so) = pbh[i];
            *(uint4*)(Bl + so) = pbl[i];
        }
        __syncthreads();   // single barrier per chunk (double buffer)

        // ---- prefetch next chunk ----
        if (kc + 1 < NCH) {
            const int off = (kc + 1) * BK + cq * 8;
#pragma unroll
            for (int i = 0; i < 2; ++i) {
                int r = crow + i * 64;
                pah[i] = *(const uint4*)(Xh + (size_t)(bm + r) * DD + off);
                pal[i] = *(const uint4*)(Xl + (size_t)(bm + r) * DD + off);
                pbh[i] = *(const uint4*)(Wh + (size_t)(bn + r) * DD + off);
                pbl[i] = *(const uint4*)(Wl + (size_t)(bn + r) * DD + off);
            }
        }

        const uint32_t AhU = smbase + (uint32_t)((kc & 1) * STAGE_B);
        const uint32_t AlU = AhU + ARR_B;
        const uint32_t BhU = AlU + ARR_B;
        const uint32_t BlU = BhU + ARR_B;

        // ---- compute: 2 k-steps of 16 ----
#pragma unroll
        for (int ks = 0; ks < 2; ++ks) {
            uint32_t ah[4][4], al[4][4], bh[4][2], bl[4][2];
            const uint32_t aoff = (uint32_t)(rowA * LDSH + ks * 16 + kofA) * 2u;
            const uint32_t boff = (uint32_t)(rowB * LDSH + ks * 16 + kofB) * 2u;
#pragma unroll
            for (int mt = 0; mt < 4; ++mt) {
                uint32_t mb = (uint32_t)((mwarp + mt * 16) * LDSH) * 2u;
                ldsm_x4(ah[mt], AhU + mb + aoff);
                ldsm_x4(al[mt], AlU + mb + aoff);
            }
#pragma unroll
            for (int p = 0; p < 2; ++p) {
                uint32_t nb = (uint32_t)((nwarp + p * 16) * LDSH) * 2u;
                uint32_t rh[4], rl[4];
                ldsm_x4(rh, BhU + nb + boff);
                ldsm_x4(rl, BlU + nb + boff);
                bh[2 * p][0] = rh[0]; bh[2 * p][1] = rh[1];
                bh[2 * p + 1][0] = rh[2]; bh[2 * p + 1][1] = rh[3];
                bl[2 * p][0] = rl[0]; bl[2 * p][1] = rl[1];
                bl[2 * p + 1][0] = rl[2]; bl[2 * p + 1][1] = rl[3];
            }
#pragma unroll
            for (int mt = 0; mt < 4; ++mt)
#pragma unroll
                for (int nt = 0; nt < 4; ++nt) {
                    mma_f16_16n8k16(acc[mt][nt], ah[mt], bh[nt]);
                    mma_f16_16n8k16(acc[mt][nt], ah[mt], bl[nt]);
                    mma_f16_16n8k16(acc[mt][nt], al[mt], bh[nt]);
                }
        }
        __syncthreads();
    }

    // ---- epilogue ----
    const float alv = alpha[0];
#pragma unroll
    for (int mt = 0; mt < 4; ++mt) {
        int r0 = bm + mwarp + mt * 16 + g;
        float p0 = 0.f, p1 = 0.f;
#pragma unroll
        for (int nt = 0; nt < 4; ++nt) {
            int cb = bn + nwarp + nt * 8 + 2 * t4;
            float b0 = 0.f, b1 = 0.f;
            if (bias) { b0 = bias[cb]; b1 = bias[cb + 1]; }
            float v0 = acc[mt][nt][0] + b0;
            float v1 = acc[mt][nt][1] + b1;
            float v2 = acc[mt][nt][2] + b0;
            float v3 = acc[mt][nt][3] + b1;
            v0 = v0 >= 0.f ? v0 : alv * v0;
            v1 = v1 >= 0.f ? v1 : alv * v1;
            v2 = v2 >= 0.f ? v2 : alv * v2;
            v3 = v3 >= 0.f ? v3 : alv * v3;
            if (MODE == 1) {
                __half h0 = __float2half_rn(v0), h1 = __float2half_rn(v1);
                __half h2 = __float2half_rn(v2), h3 = __float2half_rn(v3);
                __half2 lo01 = __halves2half2(__float2half_rn(v0 - __half2float(h0)),
                                              __float2half_rn(v1 - __half2float(h1)));
                __half2 lo23 = __halves2half2(__float2half_rn(v2 - __half2float(h2)),
                                              __float2half_rn(v3 - __half2float(h3)));
                *(__half2*)&Yh[(size_t)r0 * DD + cb]       = __halves2half2(h0, h1);
                *(__half2*)&Yl[(size_t)r0 * DD + cb]       = lo01;
                *(__half2*)&Yh[(size_t)(r0 + 8) * DD + cb] = __halves2half2(h2, h3);
                *(__half2*)&Yl[(size_t)(r0 + 8) * DD + cb] = lo23;
            } else {
                float w0 = Wo[cb], w1 = Wo[cb + 1];
                p0 = fmaf(v0, w0, fmaf(v1, w1, p0));
                p1 = fmaf(v2, w0, fmaf(v3, w1, p1));
            }
        }
        if (MODE == 2) {
            p0 += __shfl_xor_sync(0xffffffffu, p0, 1);
            p0 += __shfl_xor_sync(0xffffffffu, p0, 2);
            p1 += __shfl_xor_sync(0xffffffffu, p1, 1);
            p1 += __shfl_xor_sync(0xffffffffu, p1, 2);
            if (t4 == 0) {
                atomicAdd(&g_angles[r0],     p0);
                atomicAdd(&g_angles[r0 + 8], p1);
            }
        }
    }
}

// ---------------- edge pass: build bit-adjacency + hop-1 segment sum ----
// angles_full(d) = g_angles[d] + bo  (bo folded in here)
__global__ void edge_kernel(const int* __restrict__ ei, int E,
                            const float* __restrict__ bo)
{
    int t = blockIdx.x * blockDim.x + threadIdx.x;
    if (t >= E) return;
    int s = ei[t];
    int d = ei[E + t];
    atomicOr(&g_A[s * NW + (d >> 5)], 1u << (d & 31));
    atomicAdd(&g_acc[s], g_angles[d] + bo[0]);   // duplicates count
}

__global__ void a1_kernel(const float* __restrict__ bo)
{
    int i = blockIdx.x * blockDim.x + threadIdx.x;
    if (i < NN) g_a1[i] = (g_angles[i] + bo[0]) + 0.25f * g_acc[i];  // (0.5)^2
}

// ======================================================================
//  Hop kernels: prefix-sum neighbor extraction + 8-way unrolled row-OR
//  + coalesced broadcast-masked gather.
// ======================================================================
#define NBR_CAP 4096

template <bool STORE_A2>
__device__ __forceinline__ void hop_body(
    const unsigned* __restrict__ nbrmat,
    const float*    __restrict__ vec,
    float scale, float* __restrict__ dst)
{
    const int i = blockIdx.x;
    const int t = threadIdx.x;  // 0..127

    __shared__ unsigned short s_nbr[NBR_CAP];
    __shared__ int   s_wtot[4];
    __shared__ int   s_deg;
    __shared__ unsigned swords[NW];
    __shared__ float red[NW];

    // --- extract this row's neighbor list (deterministic order) ---
    unsigned mybits = g_A[i * NW + t];
    int cnt = __popc(mybits);
    int incl = cnt;
#pragma unroll
    for (int o = 1; o < 32; o <<= 1) {
        int v = __shfl_up_sync(0xffffffffu, incl, o);
        if ((t & 31) >= o) incl += v;
    }
    if ((t & 31) == 31) s_wtot[t >> 5] = incl;
    __syncthreads();
    int base = incl - cnt;
#pragma unroll
    for (int w = 0; w < 4; ++w)
        if (w < (t >> 5)) base += s_wtot[w];
    int pos = base;
    unsigned bb = mybits;
    while (bb) {
        int b = __ffs(bb) - 1;
        bb &= bb - 1;
        s_nbr[pos++] = (unsigned short)(t * 32 + b);
    }
    if (t == 127) s_deg = base + cnt;
    __syncthreads();
    const int deg = s_deg;

    // --- OR neighbor rows (word t), 8-way ILP ---
    unsigned accw = 0u;
    int j = 0;
    for (; j + 8 <= deg; j += 8) {
        unsigned v0 = nbrmat[s_nbr[j]     * NW + t];
        unsigned v1 = nbrmat[s_nbr[j + 1] * NW + t];
        unsigned v2 = nbrmat[s_nbr[j + 2] * NW + t];
        unsigned v3 = nbrmat[s_nbr[j + 3] * NW + t];
        unsigned v4 = nbrmat[s_nbr[j + 4] * NW + t];
        unsigned v5 = nbrmat[s_nbr[j + 5] * NW + t];
        unsigned v6 = nbrmat[s_nbr[j + 6] * NW + t];
        unsigned v7 = nbrmat[s_nbr[j + 7] * NW + t];
        accw |= ((v0 | v1) | (v2 | v3)) | ((v4 | v5) | (v6 | v7));
    }
    for (; j < deg; ++j) accw |= nbrmat[s_nbr[j] * NW + t];

    if (STORE_A2) g_A2[i * NW + t] = accw;
    swords[t] = accw;
    __syncthreads();

    // --- coalesced masked gather: element k*128+t, warp-uniform word ---
    float p = 0.f;
#pragma unroll 4
    for (int k = 0; k < 32; ++k) {
        int idx = k * 128 + t;
        unsigned wrd = swords[idx >> 5];
        p += vec[idx] * (float)((wrd >> (idx & 31)) & 1u);
    }
    red[t] = p;
    __syncthreads();
#pragma unroll
    for (int s = 64; s; s >>= 1) {
        if (t < s) red[t] += red[t + s];
        __syncthreads();
    }
    if (t == 0) dst[i] = vec[i] + scale * red[0];
}

__global__ __launch_bounds__(128) void hop2_kernel()
{
    hop_body<true>(g_A, g_a1, 1.0f / 9.0f, g_a2);
}

__global__ __launch_bounds__(128) void hop3_kernel(float* __restrict__ out)
{
    hop_body<false>(g_A2, g_a2, 1.0f / 16.0f, out);
}

// ---------------------------- launch ------------------------------------
extern "C" void kernel_launch(void* const* d_in, const int* in_sizes, int n_in,
                              void* d_out, int out_size)
{
    const float* coeffs = (const float*)d_in[0];
    const int*   eidx   = (const int*)  d_in[1];
    const float* W0     = (const float*)d_in[2];
    const float* b0     = (const float*)d_in[3];
    const float* a0     = (const float*)d_in[4];
    const float* W1     = (const float*)d_in[5];
    const float* a1p    = (const float*)d_in[6];
    const float* W2     = (const float*)d_in[7];
    const float* a2p    = (const float*)d_in[8];
    const float* Wo     = (const float*)d_in[9];
    const float* bo     = (const float*)d_in[10];
    float* out = (float*)d_out;

    const int E = in_sizes[1] / 2;

    __half *p_xh, *p_xl, *p_yh, *p_yl, *p_wh, *p_wl;
    cudaGetSymbolAddress((void**)&p_xh, g_xh);
    cudaGetSymbolAddress((void**)&p_xl, g_xl);
    cudaGetSymbolAddress((void**)&p_yh, g_yh);
    cudaGetSymbolAddress((void**)&p_yl, g_yl);
    cudaGetSymbolAddress((void**)&p_wh, g_wh);
    cudaGetSymbolAddress((void**)&p_wl, g_wl);

    cudaFuncSetAttribute(tc_gemm<1>, cudaFuncAttributeMaxDynamicSharedMemorySize, GEMM_SMEM);
    cudaFuncSetAttribute(tc_gemm<2>, cudaFuncAttributeMaxDynamicSharedMemorySize, GEMM_SMEM);

    // 1) zero A bitmatrix + hop-1 accumulator + angles
    zero_kernel<<<1024, 256>>>();

    // 2) pre-split coeffs and weights to fp16 hi/lo
    split_kernel<<<(NN * DD / 4 + 255) / 256, 256>>>(coeffs, p_xh, p_xl, NN * DD);
    splitw_kernel<<<(3 * DD * DD / 4 + 255) / 256, 256>>>(W0, W1, W2, p_wh, p_wl);

    // 3) MLP: layers 1-2 split-fp16 GEMM+PReLU; layer 3 fused with output head
    dim3 ggrid(DD / BN, NN / BM);   // (4, 32) = 128 CTAs
    tc_gemm<1><<<ggrid, NT, GEMM_SMEM>>>(p_xh, p_xl, p_wh + 0 * DD * DD, p_wl + 0 * DD * DD,
                                         b0,      a0,  nullptr, p_yh, p_yl);
    tc_gemm<1><<<ggrid, NT, GEMM_SMEM>>>(p_yh, p_yl, p_wh + 1 * DD * DD, p_wl + 1 * DD * DD,
                                         nullptr, a1p, nullptr, p_xh, p_xl);
    tc_gemm<2><<<ggrid, NT, GEMM_SMEM>>>(p_xh, p_xl, p_wh + 2 * DD * DD, p_wl + 2 * DD * DD,
                                         nullptr, a2p, Wo, nullptr, nullptr);

    // 4) edges: bit adjacency + hop-1 raw segment sum (bo folded in)
    edge_kernel<<<(E + 255) / 256, 256>>>(eidx, E, bo);
    a1_kernel<<<(NN + 255) / 256, 256>>>(bo);

    // 5) hop 2 (materializes A2 bits) and hop 3 (fused, writes output)
    hop2_kernel<<<NN, 128>>>();
    hop3_kernel<<<NN, 128>>>(out);
}

// round 15
// speedup vs baseline: 1.0477x; 1.0472x over previous
#include <cuda_runtime.h>
#include <cuda_bf16.h>
#include <cuda_fp16.h>
#include <cstdint>

// Problem constants (fixed by the dataset)
#define NN 4096      // nodes
#define DD 512       // feature dim
#define NW 128       // bitmask words per row (4096/32)

// ---------------- device scratch (no allocation allowed) ----------------
__device__ float    g_angles[NN];
__device__ float    g_acc[NN];
__device__ float    g_a1[NN];
__device__ float    g_a2[NN];
__device__ unsigned g_A [NN * NW];
__device__ unsigned g_A2[NN * NW];
__device__ unsigned g_A3[NN * NW];
// fp16 split buffers
__device__ __align__(16) __half g_xh[NN * DD];
__device__ __align__(16) __half g_xl[NN * DD];
__device__ __align__(16) __half g_yh[NN * DD];
__device__ __align__(16) __half g_yl[NN * DD];
__device__ __align__(16) __half g_wh[3 * DD * DD];
__device__ __align__(16) __half g_wl[3 * DD * DD];

// ---------------- zero adjacency (side stream) --------------------------
__global__ void zeroA_kernel() {
    int idx = blockIdx.x * blockDim.x + threadIdx.x;
    int total = NN * NW;
    for (int i = idx; i < total; i += gridDim.x * blockDim.x) g_A[i] = 0u;
}

// ---------------- fp32 -> (fp16 hi, fp16 lo) split ----------------------
__device__ __forceinline__ void split_store(const float* __restrict__ src,
                                            __half* __restrict__ h,
                                            __half* __restrict__ l, int i)
{
    float4 v = *(const float4*)(src + i);
    __half hx = __float2half_rn(v.x), hy = __float2half_rn(v.y);
    __half hz = __float2half_rn(v.z), hw = __float2half_rn(v.w);
    __half2 h01 = __halves2half2(hx, hy), h23 = __halves2half2(hz, hw);
    __half2 l01 = __halves2half2(__float2half_rn(v.x - __half2float(hx)),
                                 __float2half_rn(v.y - __half2float(hy)));
    __half2 l23 = __halves2half2(__float2half_rn(v.z - __half2float(hz)),
                                 __float2half_rn(v.w - __half2float(hw)));
    *(__half2*)(h + i)     = h01;
    *(__half2*)(h + i + 2) = h23;
    *(__half2*)(l + i)     = l01;
    *(__half2*)(l + i + 2) = l23;
}

__global__ void split_kernel(const float* __restrict__ src,
                             __half* __restrict__ h, __half* __restrict__ l,
                             int n)
{
    int idx = blockIdx.x * blockDim.x + threadIdx.x;
    int i = idx * 4;
    if (i >= n) return;
    split_store(src, h, l, i);
}

// merged 3-weight split (W0, W1, W2 -> g_wh/g_wl slabs) + zero acc/angles
__global__ void splitw_kernel(const float* __restrict__ W0,
                              const float* __restrict__ W1,
                              const float* __restrict__ W2,
                              __half* __restrict__ h, __half* __restrict__ l)
{
    const int per = DD * DD / 4;
    int idx = blockIdx.x * blockDim.x + threadIdx.x;
    if (idx < NN) { g_acc[idx] = 0.0f; g_angles[idx] = 0.0f; }
    if (idx >= 3 * per) return;
    int arr = idx / per;
    int i = (idx - arr * per) * 4;
    const float* src = arr == 0 ? W0 : (arr == 1 ? W1 : W2);
    split_store(src, h + arr * DD * DD, l + arr * DD * DD, i);
}

// ======================================================================
//  3xFP16 split GEMM, cp.async 3-stage pipeline + ldmatrix + mma.sync
//  (R12 configuration -- best measured end-to-end).
//  MODE 1: store Y as split fp16 pair. MODE 2: fused output head.
//  CTA: 128(M) x 128(N), 512 threads (16 warps 4x4), warp 32x32.
// ======================================================================
#define BM 128
#define BN 128
#define BK 32
#define NT 512
#define LDSH 40                     // padded row stride in halves
#define ARR_B  (128 * LDSH * 2)     // 10240 B per array
#define STAGE_B (4 * ARR_B)         // 40960 B per stage
#define NSTAGE 3
#define GEMM_SMEM (NSTAGE * STAGE_B)
#define NCH (DD / BK)               // 16

__device__ __forceinline__ void mma_f16_16n8k16(
    float c[4], const uint32_t a[4], const uint32_t b[2])
{
    asm volatile(
        "mma.sync.aligned.m16n8k16.row.col.f32.f16.f16.f32 "
        "{%0,%1,%2,%3}, {%4,%5,%6,%7}, {%8,%9}, {%0,%1,%2,%3};"
        : "+f"(c[0]), "+f"(c[1]), "+f"(c[2]), "+f"(c[3])
        : "r"(a[0]), "r"(a[1]), "r"(a[2]), "r"(a[3]),
          "r"(b[0]), "r"(b[1]));
}

__device__ __forceinline__ void ldsm_x4(uint32_t r[4], uint32_t addr) {
    asm volatile(
        "ldmatrix.sync.aligned.m8n8.x4.shared.b16 {%0,%1,%2,%3}, [%4];"
        : "=r"(r[0]), "=r"(r[1]), "=r"(r[2]), "=r"(r[3]) : "r"(addr));
}

__device__ __forceinline__ void cpa16(uint32_t dst, const void* src) {
    asm volatile("cp.async.cg.shared.global [%0], [%1], 16;"
                 :: "r"(dst), "l"(src) : "memory");
}

template <int MODE>
__global__ __launch_bounds__(NT, 1) void tc_gemm(
    const __half* __restrict__ Xh, const __half* __restrict__ Xl,
    const __half* __restrict__ Wh, const __half* __restrict__ Wl,
    const float* __restrict__ bias, const float* __restrict__ alpha,
    const float* __restrict__ Wo,
    __half* __restrict__ Yh, __half* __restrict__ Yl)
{
    extern __shared__ char sm[];

    const int tid  = threadIdx.x;
    const int lane = tid & 31;
    const int wid  = tid >> 5;          // 0..15
    const int g    = lane >> 2;
    const int t4   = lane & 3;
    const int mwarp = (wid >> 2) * 32;  // 0,32,64,96
    const int nwarp = (wid & 3) * 32;   // 0,32,64,96
    const int bm = blockIdx.y * BM;
    const int bn = blockIdx.x * BN;

    // cp.async mapping: per array, 512 x 16B ops; exactly 1 per thread
    const int crow = tid >> 2;      // 0..127
    const int cq   = tid & 3;       // 16B unit within 64B row chunk

    const int rowA = lane & 15;
    const int kofA = (lane & 16) ? 8 : 0;
    const int rowB = (lane & 7) + ((lane & 16) ? 8 : 0);
    const int kofB = (lane & 8) ? 8 : 0;

    const uint32_t smbase = (uint32_t)__cvta_generic_to_shared(sm);

    float acc[2][4][4];
#pragma unroll
    for (int i = 0; i < 2; ++i)
#pragma unroll
        for (int j = 0; j < 4; ++j)
#pragma unroll
            for (int q = 0; q < 4; ++q) acc[i][j][q] = 0.0f;

    auto issue = [&](int kc) {
        const uint32_t st = smbase + (uint32_t)(kc % NSTAGE) * STAGE_B;
        uint32_t so = (uint32_t)(crow * (LDSH * 2) + cq * 16);
        size_t goA = (size_t)(bm + crow) * DD + kc * BK + cq * 8;
        size_t goB = (size_t)(bn + crow) * DD + kc * BK + cq * 8;
        cpa16(st + 0 * ARR_B + so, Xh + goA);
        cpa16(st + 1 * ARR_B + so, Xl + goA);
        cpa16(st + 2 * ARR_B + so, Wh + goB);
        cpa16(st + 3 * ARR_B + so, Wl + goB);
        asm volatile("cp.async.commit_group;" ::: "memory");
    };

    issue(0);
    issue(1);

    for (int kc = 0; kc < NCH; ++kc) {
        if (kc < NCH - 1)
            asm volatile("cp.async.wait_group 1;" ::: "memory");
        else
            asm volatile("cp.async.wait_group 0;" ::: "memory");
        __syncthreads();
        if (kc + 2 < NCH) issue(kc + 2);

        const uint32_t st  = smbase + (uint32_t)(kc % NSTAGE) * STAGE_B;
        const uint32_t AhU = st;
        const uint32_t AlU = st + ARR_B;
        const uint32_t BhU = st + 2 * ARR_B;
        const uint32_t BlU = st + 3 * ARR_B;

#pragma unroll
        for (int ks = 0; ks < 2; ++ks) {
            uint32_t ah[2][4], al[2][4], bh[4][2], bl[4][2];
            const uint32_t aoff = (uint32_t)(rowA * LDSH + ks * 16 + kofA) * 2u;
            const uint32_t boff = (uint32_t)(rowB * LDSH + ks * 16 + kofB) * 2u;
#pragma unroll
            for (int mt = 0; mt < 2; ++mt) {
                uint32_t mb = (uint32_t)((mwarp + mt * 16) * LDSH) * 2u;
                ldsm_x4(ah[mt], AhU + mb + aoff);
                ldsm_x4(al[mt], AlU + mb + aoff);
            }
#pragma unroll
            for (int p = 0; p < 2; ++p) {
                uint32_t nb = (uint32_t)((nwarp + p * 16) * LDSH) * 2u;
                uint32_t rh[4], rl[4];
                ldsm_x4(rh, BhU + nb + boff);
                ldsm_x4(rl, BlU + nb + boff);
                bh[2 * p][0] = rh[0]; bh[2 * p][1] = rh[1];
                bh[2 * p + 1][0] = rh[2]; bh[2 * p + 1][1] = rh[3];
                bl[2 * p][0] = rl[0]; bl[2 * p][1] = rl[1];
                bl[2 * p + 1][0] = rl[2]; bl[2 * p + 1][1] = rl[3];
            }
#pragma unroll
            for (int mt = 0; mt < 2; ++mt)
#pragma unroll
                for (int nt = 0; nt < 4; ++nt) {
                    mma_f16_16n8k16(acc[mt][nt], ah[mt], bh[nt]);
                    mma_f16_16n8k16(acc[mt][nt], ah[mt], bl[nt]);
                    mma_f16_16n8k16(acc[mt][nt], al[mt], bh[nt]);
                }
        }
    }

    // ---- epilogue ----
    const float alv = alpha[0];
#pragma unroll
    for (int mt = 0; mt < 2; ++mt) {
        int r0 = bm + mwarp + mt * 16 + g;
        float p0 = 0.f, p1 = 0.f;
#pragma unroll
        for (int nt = 0; nt < 4; ++nt) {
            int cb = bn + nwarp + nt * 8 + 2 * t4;
            float b0 = 0.f, b1 = 0.f;
            if (bias) { b0 = bias[cb]; b1 = bias[cb + 1]; }
            float v0 = acc[mt][nt][0] + b0;
            float v1 = acc[mt][nt][1] + b1;
            float v2 = acc[mt][nt][2] + b0;
            float v3 = acc[mt][nt][3] + b1;
            v0 = v0 >= 0.f ? v0 : alv * v0;
            v1 = v1 >= 0.f ? v1 : alv * v1;
            v2 = v2 >= 0.f ? v2 : alv * v2;
            v3 = v3 >= 0.f ? v3 : alv * v3;
            if (MODE == 1) {
                __half h0 = __float2half_rn(v0), h1 = __float2half_rn(v1);
                __half h2 = __float2half_rn(v2), h3 = __float2half_rn(v3);
                __half2 lo01 = __halves2half2(__float2half_rn(v0 - __half2float(h0)),
                                              __float2half_rn(v1 - __half2float(h1)));
                __half2 lo23 = __halves2half2(__float2half_rn(v2 - __half2float(h2)),
                                              __float2half_rn(v3 - __half2float(h3)));
                *(__half2*)&Yh[(size_t)r0 * DD + cb]       = __halves2half2(h0, h1);
                *(__half2*)&Yl[(size_t)r0 * DD + cb]       = lo01;
                *(__half2*)&Yh[(size_t)(r0 + 8) * DD + cb] = __halves2half2(h2, h3);
                *(__half2*)&Yl[(size_t)(r0 + 8) * DD + cb] = lo23;
            } else {
                float w0 = Wo[cb], w1 = Wo[cb + 1];
                p0 = fmaf(v0, w0, fmaf(v1, w1, p0));
                p1 = fmaf(v2, w0, fmaf(v3, w1, p1));
            }
        }
        if (MODE == 2) {
            p0 += __shfl_xor_sync(0xffffffffu, p0, 1);
            p0 += __shfl_xor_sync(0xffffffffu, p0, 2);
            p1 += __shfl_xor_sync(0xffffffffu, p1, 1);
            p1 += __shfl_xor_sync(0xffffffffu, p1, 2);
            if (t4 == 0) {
                atomicAdd(&g_angles[r0],     p0);
                atomicAdd(&g_angles[r0 + 8], p1);
            }
        }
    }
}

// ---------------- edge passes -------------------------------------------
// adjacency build (side stream; only touches g_A + eidx)
__global__ void edge_adj_kernel(const int* __restrict__ ei, int E)
{
    int t = blockIdx.x * blockDim.x + threadIdx.x;
    if (t >= E) return;
    int s = ei[t];
    int d = ei[E + t];
    atomicOr(&g_A[s * NW + (d >> 5)], 1u << (d & 31));
}

// hop-1 raw segment sum (needs angles); angles_full(d) = g_angles[d] + bo
__global__ void edge_sum_kernel(const int* __restrict__ ei, int E,
                                const float* __restrict__ bo)
{
    int t = blockIdx.x * blockDim.x + threadIdx.x;
    if (t >= E) return;
    int s = ei[t];
    int d = ei[E + t];
    atomicAdd(&g_acc[s], g_angles[d] + bo[0]);   // duplicates count
}

__global__ void a1_kernel(const float* __restrict__ bo)
{
    int i = blockIdx.x * blockDim.x + threadIdx.x;
    if (i < NN) g_a1[i] = (g_angles[i] + bo[0]) + 0.25f * g_acc[i];  // (0.5)^2
}

// ======================================================================
//  Bit-matrix power kernels (side stream): prefix-sum neighbor
//  extraction + 8-way unrolled row-OR.  dst = bool(nbr-OR of nbrmat).
// ======================================================================
__global__ __launch_bounds__(128) void hop_bits_kernel(
    const unsigned* __restrict__ nbrmat, unsigned* __restrict__ dstmat)
{
    const int i = blockIdx.x;
    const int t = threadIdx.x;  // 0..127

    __shared__ unsigned short s_nbr[4096];
    __shared__ int s_wtot[4];
    __shared__ int s_deg;

    // --- extract row i's 1-hop neighbor list (deterministic order) ---
    unsigned mybits = g_A[i * NW + t];
    int cnt = __popc(mybits);
    int incl = cnt;
#pragma unroll
    for (int o = 1; o < 32; o <<= 1) {
        int v = __shfl_up_sync(0xffffffffu, incl, o);
        if ((t & 31) >= o) incl += v;
    }
    if ((t & 31) == 31) s_wtot[t >> 5] = incl;
    __syncthreads();
    int base = incl - cnt;
#pragma unroll
    for (int w = 0; w < 4; ++w)
        if (w < (t >> 5)) base += s_wtot[w];
    int pos = base;
    unsigned bb = mybits;
    while (bb) {
        int b = __ffs(bb) - 1;
        bb &= bb - 1;
        s_nbr[pos++] = (unsigned short)(t * 32 + b);
    }
    if (t == 127) s_deg = base + cnt;
    __syncthreads();
    const int deg = s_deg;

    // --- OR neighbor rows (word t), 8-way ILP ---
    unsigned accw = 0u;
    int j = 0;
    for (; j + 8 <= deg; j += 8) {
        unsigned v0 = nbrmat[s_nbr[j]     * NW + t];
        unsigned v1 = nbrmat[s_nbr[j + 1] * NW + t];
        unsigned v2 = nbrmat[s_nbr[j + 2] * NW + t];
        unsigned v3 = nbrmat[s_nbr[j + 3] * NW + t];
        unsigned v4 = nbrmat[s_nbr[j + 4] * NW + t];
        unsigned v5 = nbrmat[s_nbr[j + 5] * NW + t];
        unsigned v6 = nbrmat[s_nbr[j + 6] * NW + t];
        unsigned v7 = nbrmat[s_nbr[j + 7] * NW + t];
        accw |= ((v0 | v1) | (v2 | v3)) | ((v4 | v5) | (v6 | v7));
    }
    for (; j < deg; ++j) accw |= nbrmat[s_nbr[j] * NW + t];

    dstmat[i * NW + t] = accw;
}

// ======================================================================
//  Gather kernels (critical path, cheap): dst[i] = vec[i] +
//  scale * sum_{j in bits(mat row i)} vec[j].
// ======================================================================
__global__ __launch_bounds__(128) void gather_kernel(
    const unsigned* __restrict__ mat, const float* __restrict__ vec,
    float scale, float* __restrict__ dst)
{
    const int i = blockIdx.x;
    const int t = threadIdx.x;

    __shared__ unsigned swords[NW];
    __shared__ float red[NW];

    swords[t] = mat[i * NW + t];
    __syncthreads();

    float p = 0.f;
#pragma unroll 4
    for (int k = 0; k < 32; ++k) {
        int idx = k * 128 + t;
        unsigned wrd = swords[idx >> 5];
        p += vec[idx] * (float)((wrd >> (idx & 31)) & 1u);
    }
    red[t] = p;
    __syncthreads();
#pragma unroll
    for (int s = 64; s; s >>= 1) {
        if (t < s) red[t] += red[t + s];
        __syncthreads();
    }
    if (t == 0) dst[i] = vec[i] + scale * red[0];
}

// ---------------------------- launch ------------------------------------
extern "C" void kernel_launch(void* const* d_in, const int* in_sizes, int n_in,
                              void* d_out, int out_size)
{
    const float* coeffs = (const float*)d_in[0];
    const int*   eidx   = (const int*)  d_in[1];
    const float* W0     = (const float*)d_in[2];
    const float* b0     = (const float*)d_in[3];
    const float* a0     = (const float*)d_in[4];
    const float* W1     = (const float*)d_in[5];
    const float* a1p    = (const float*)d_in[6];
    const float* W2     = (const float*)d_in[7];
    const float* a2p    = (const float*)d_in[8];
    const float* Wo     = (const float*)d_in[9];
    const float* bo     = (const float*)d_in[10];
    float* out = (float*)d_out;

    const int E = in_sizes[1] / 2;

    __half *p_xh, *p_xl, *p_yh, *p_yl, *p_wh, *p_wl;
    float *p_a1, *p_a2;
    unsigned *p_A2, *p_A3;
    cudaGetSymbolAddress((void**)&p_xh, g_xh);
    cudaGetSymbolAddress((void**)&p_xl, g_xl);
    cudaGetSymbolAddress((void**)&p_yh, g_yh);
    cudaGetSymbolAddress((void**)&p_yl, g_yl);
    cudaGetSymbolAddress((void**)&p_wh, g_wh);
    cudaGetSymbolAddress((void**)&p_wl, g_wl);
    cudaGetSymbolAddress((void**)&p_a1, g_a1);
    cudaGetSymbolAddress((void**)&p_a2, g_a2);
    cudaGetSymbolAddress((void**)&p_A2, g_A2);
    cudaGetSymbolAddress((void**)&p_A3, g_A3);
    unsigned* p_A;
    cudaGetSymbolAddress((void**)&p_A, g_A);

    cudaFuncSetAttribute(tc_gemm<1>, cudaFuncAttributeMaxDynamicSharedMemorySize, GEMM_SMEM);
    cudaFuncSetAttribute(tc_gemm<2>, cudaFuncAttributeMaxDynamicSharedMemorySize, GEMM_SMEM);

    // one-time side stream + events (same graph shape every call)
    static cudaStream_t s2 = nullptr;
    static cudaEvent_t evFork = nullptr, evJoin = nullptr;
    if (!s2) {
        cudaStreamCreateWithFlags(&s2, cudaStreamNonBlocking);
        cudaEventCreateWithFlags(&evFork, cudaEventDisableTiming);
        cudaEventCreateWithFlags(&evJoin, cudaEventDisableTiming);
    }

    // ---- fork: side stream computes adjacency powers (A, A2, A3) ----
    cudaEventRecord(evFork, 0);
    cudaStreamWaitEvent(s2, evFork, 0);
    zeroA_kernel<<<512, 256, 0, s2>>>();
    edge_adj_kernel<<<(E + 255) / 256, 256, 0, s2>>>(eidx, E);
    hop_bits_kernel<<<NN, 128, 0, s2>>>(p_A,  p_A2);   // A2 = bool(A@A)
    hop_bits_kernel<<<NN, 128, 0, s2>>>(p_A2, p_A3);   // A3 = bool(A@A2)
    cudaEventRecord(evJoin, s2);

    // ---- main stream: splits + MLP chain ----
    split_kernel<<<(NN * DD / 4 + 255) / 256, 256>>>(coeffs, p_xh, p_xl, NN * DD);
    splitw_kernel<<<(3 * DD * DD / 4 + 255) / 256, 256>>>(W0, W1, W2, p_wh, p_wl);

    dim3 ggrid(DD / BN, NN / BM);   // (4, 32) = 128 CTAs
    tc_gemm<1><<<ggrid, NT, GEMM_SMEM>>>(p_xh, p_xl, p_wh + 0 * DD * DD, p_wl + 0 * DD * DD,
                                         b0,      a0,  nullptr, p_yh, p_yl);
    tc_gemm<1><<<ggrid, NT, GEMM_SMEM>>>(p_yh, p_yl, p_wh + 1 * DD * DD, p_wl + 1 * DD * DD,
                                         nullptr, a1p, nullptr, p_xh, p_xl);
    tc_gemm<2><<<ggrid, NT, GEMM_SMEM>>>(p_xh, p_xl, p_wh + 2 * DD * DD, p_wl + 2 * DD * DD,
                                         nullptr, a2p, Wo, nullptr, nullptr);

    // ---- hop-1 (needs angles) ----
    edge_sum_kernel<<<(E + 255) / 256, 256>>>(eidx, E, bo);
    a1_kernel<<<(NN + 255) / 256, 256>>>(bo);

    // ---- join: gathers need A2/A3 bits ----
    cudaStreamWaitEvent(0, evJoin, 0);
    gather_kernel<<<NN, 128>>>(p_A2, p_a1, 1.0f / 9.0f,  p_a2);
    gather_kernel<<<NN, 128>>>(p_A3, p_a2, 1.0f / 16.0f, out);
}

// round 17
// speedup vs baseline: 1.4343x; 1.3690x over previous
#include <cuda_runtime.h>
#include <cuda_bf16.h>
#include <cuda_fp16.h>
#include <cstdint>

// Problem constants (fixed by the dataset)
#define NN 4096      // nodes
#define DD 512       // feature dim
#define NW 128       // bitmask words per row (4096/32)

// ---------------- device scratch (no allocation allowed) ----------------
__device__ float    g_angles[NN];
__device__ float    g_acc[NN];
__device__ float    g_a1[NN];
__device__ float    g_a2[NN];
__device__ unsigned g_A [NN * NW];
__device__ unsigned g_A2[NN * NW];
__device__ unsigned g_A3[NN * NW];
// fp16 buffers: activations (hi only) ping/pong, weights hi/lo
__device__ __align__(16) __half g_xh[NN * DD];
__device__ __align__(16) __half g_yh[NN * DD];
__device__ __align__(16) __half g_wh[3 * DD * DD];
__device__ __align__(16) __half g_wl[3 * DD * DD];

// ---------------- zero adjacency (side stream) --------------------------
__global__ void zeroA_kernel() {
    int idx = blockIdx.x * blockDim.x + threadIdx.x;
    int total = NN * NW;
    for (int i = idx; i < total; i += gridDim.x * blockDim.x) g_A[i] = 0u;
}

// ---------------- fp32 -> fp16 (hi only, activations) -------------------
__global__ void splitx_kernel(const float* __restrict__ src,
                              __half* __restrict__ h, int n)
{
    int i = (blockIdx.x * blockDim.x + threadIdx.x) * 4;
    if (i >= n) return;
    float4 v = *(const float4*)(src + i);
    __half2 h01 = __halves2half2(__float2half_rn(v.x), __float2half_rn(v.y));
    __half2 h23 = __halves2half2(__float2half_rn(v.z), __float2half_rn(v.w));
    *(__half2*)(h + i)     = h01;
    *(__half2*)(h + i + 2) = h23;
}

// ---------------- fp32 -> (fp16 hi, fp16 lo) for weights ----------------
__device__ __forceinline__ void split_store(const float* __restrict__ src,
                                            __half* __restrict__ h,
                                            __half* __restrict__ l, int i)
{
    float4 v = *(const float4*)(src + i);
    __half hx = __float2half_rn(v.x), hy = __float2half_rn(v.y);
    __half hz = __float2half_rn(v.z), hw = __float2half_rn(v.w);
    __half2 h01 = __halves2half2(hx, hy), h23 = __halves2half2(hz, hw);
    __half2 l01 = __halves2half2(__float2half_rn(v.x - __half2float(hx)),
                                 __float2half_rn(v.y - __half2float(hy)));
    __half2 l23 = __halves2half2(__float2half_rn(v.z - __half2float(hz)),
                                 __float2half_rn(v.w - __half2float(hw)));
    *(__half2*)(h + i)     = h01;
    *(__half2*)(h + i + 2) = h23;
    *(__half2*)(l + i)     = l01;
    *(__half2*)(l + i + 2) = l23;
}

// merged 3-weight split (W0, W1, W2 -> g_wh/g_wl slabs) + zero acc/angles
__global__ void splitw_kernel(const float* __restrict__ W0,
                              const float* __restrict__ W1,
                              const float* __restrict__ W2,
                              __half* __restrict__ h, __half* __restrict__ l)
{
    const int per = DD * DD / 4;
    int idx = blockIdx.x * blockDim.x + threadIdx.x;
    if (idx < NN) { g_acc[idx] = 0.0f; g_angles[idx] = 0.0f; }
    if (idx >= 3 * per) return;
    int arr = idx / per;
    int i = (idx - arr * per) * 4;
    const float* src = arr == 0 ? W0 : (arr == 1 ? W1 : W2);
    split_store(src, h + arr * DD * DD, l + arr * DD * DD, i);
}

// ======================================================================
//  2-term FP16 split GEMM (weights split hi/lo, activations fp16):
//     Y = prelu(Xh@Wh^T + Xh@Wl^T + bias, alpha)
//  cp.async 3-stage pipeline + ldmatrix + mma.sync (R12 skeleton).
//  MODE 1: store Y as fp16 (hi). MODE 2: fused output head.
//  CTA: 128(M) x 128(N), 512 threads (16 warps 4x4), warp 32x32.
// ======================================================================
#define BM 128
#define BN 128
#define BK 32
#define NT 512
#define LDSH 40                     // padded row stride in halves
#define ARR_B  (128 * LDSH * 2)     // 10240 B per array
#define STAGE_B (3 * ARR_B)         // 30720 B per stage (Ah, Bh, Bl)
#define NSTAGE 3
#define GEMM_SMEM (NSTAGE * STAGE_B)
#define NCH (DD / BK)               // 16

__device__ __forceinline__ void mma_f16_16n8k16(
    float c[4], const uint32_t a[4], const uint32_t b[2])
{
    asm volatile(
        "mma.sync.aligned.m16n8k16.row.col.f32.f16.f16.f32 "
        "{%0,%1,%2,%3}, {%4,%5,%6,%7}, {%8,%9}, {%0,%1,%2,%3};"
        : "+f"(c[0]), "+f"(c[1]), "+f"(c[2]), "+f"(c[3])
        : "r"(a[0]), "r"(a[1]), "r"(a[2]), "r"(a[3]),
          "r"(b[0]), "r"(b[1]));
}

__device__ __forceinline__ void ldsm_x4(uint32_t r[4], uint32_t addr) {
    asm volatile(
        "ldmatrix.sync.aligned.m8n8.x4.shared.b16 {%0,%1,%2,%3}, [%4];"
        : "=r"(r[0]), "=r"(r[1]), "=r"(r[2]), "=r"(r[3]) : "r"(addr));
}

__device__ __forceinline__ void cpa16(uint32_t dst, const void* src) {
    asm volatile("cp.async.cg.shared.global [%0], [%1], 16;"
                 :: "r"(dst), "l"(src) : "memory");
}

template <int MODE>
__global__ __launch_bounds__(NT, 1) void tc_gemm(
    const __half* __restrict__ Xh,
    const __half* __restrict__ Wh, const __half* __restrict__ Wl,
    const float* __restrict__ bias, const float* __restrict__ alpha,
    const float* __restrict__ Wo,
    __half* __restrict__ Yh)
{
    extern __shared__ char sm[];

    const int tid  = threadIdx.x;
    const int lane = tid & 31;
    const int wid  = tid >> 5;          // 0..15
    const int g    = lane >> 2;
    const int t4   = lane & 3;
    const int mwarp = (wid >> 2) * 32;  // 0,32,64,96
    const int nwarp = (wid & 3) * 32;   // 0,32,64,96
    const int bm = blockIdx.y * BM;
    const int bn = blockIdx.x * BN;

    // cp.async mapping: per array, 512 x 16B ops; 1 per thread per array
    const int crow = tid >> 2;      // 0..127
    const int cq   = tid & 3;       // 16B unit within 64B row chunk

    const int rowA = lane & 15;
    const int kofA = (lane & 16) ? 8 : 0;
    const int rowB = (lane & 7) + ((lane & 16) ? 8 : 0);
    const int kofB = (lane & 8) ? 8 : 0;

    const uint32_t smbase = (uint32_t)__cvta_generic_to_shared(sm);

    float acc[2][4][4];
#pragma unroll
    for (int i = 0; i < 2; ++i)
#pragma unroll
        for (int j = 0; j < 4; ++j)
#pragma unroll
            for (int q = 0; q < 4; ++q) acc[i][j][q] = 0.0f;

    auto issue = [&](int kc) {
        const uint32_t st = smbase + (uint32_t)(kc % NSTAGE) * STAGE_B;
        uint32_t so = (uint32_t)(crow * (LDSH * 2) + cq * 16);
        size_t goA = (size_t)(bm + crow) * DD + kc * BK + cq * 8;
        size_t goB = (size_t)(bn + crow) * DD + kc * BK + cq * 8;
        cpa16(st + 0 * ARR_B + so, Xh + goA);
        cpa16(st + 1 * ARR_B + so, Wh + goB);
        cpa16(st + 2 * ARR_B + so, Wl + goB);
        asm volatile("cp.async.commit_group;" ::: "memory");
    };

    issue(0);
    issue(1);

    for (int kc = 0; kc < NCH; ++kc) {
        if (kc < NCH - 1)
            asm volatile("cp.async.wait_group 1;" ::: "memory");
        else
            asm volatile("cp.async.wait_group 0;" ::: "memory");
        __syncthreads();
        if (kc + 2 < NCH) issue(kc + 2);

        const uint32_t st  = smbase + (uint32_t)(kc % NSTAGE) * STAGE_B;
        const uint32_t AhU = st;
        const uint32_t BhU = st + ARR_B;
        const uint32_t BlU = st + 2 * ARR_B;

#pragma unroll
        for (int ks = 0; ks < 2; ++ks) {
            uint32_t ah[2][4], bh[4][2], bl[4][2];
            const uint32_t aoff = (uint32_t)(rowA * LDSH + ks * 16 + kofA) * 2u;
            const uint32_t boff = (uint32_t)(rowB * LDSH + ks * 16 + kofB) * 2u;
#pragma unroll
            for (int mt = 0; mt < 2; ++mt) {
                uint32_t mb = (uint32_t)((mwarp + mt * 16) * LDSH) * 2u;
                ldsm_x4(ah[mt], AhU + mb + aoff);
            }
#pragma unroll
            for (int p = 0; p < 2; ++p) {
                uint32_t nb = (uint32_t)((nwarp + p * 16) * LDSH) * 2u;
                uint32_t rh[4], rl[4];
                ldsm_x4(rh, BhU + nb + boff);
                ldsm_x4(rl, BlU + nb + boff);
                bh[2 * p][0] = rh[0]; bh[2 * p][1] = rh[1];
                bh[2 * p + 1][0] = rh[2]; bh[2 * p + 1][1] = rh[3];
                bl[2 * p][0] = rl[0]; bl[2 * p][1] = rl[1];
                bl[2 * p + 1][0] = rl[2]; bl[2 * p + 1][1] = rl[3];
            }
#pragma unroll
            for (int mt = 0; mt < 2; ++mt)
#pragma unroll
                for (int nt = 0; nt < 4; ++nt) {
                    mma_f16_16n8k16(acc[mt][nt], ah[mt], bh[nt]);
                    mma_f16_16n8k16(acc[mt][nt], ah[mt], bl[nt]);
                }
        }
    }

    // ---- epilogue ----
    const float alv = alpha[0];
#pragma unroll
    for (int mt = 0; mt < 2; ++mt) {
        int r0 = bm + mwarp + mt * 16 + g;
        float p0 = 0.f, p1 = 0.f;
#pragma unroll
        for (int nt = 0; nt < 4; ++nt) {
            int cb = bn + nwarp + nt * 8 + 2 * t4;
            float b0 = 0.f, b1 = 0.f;
            if (bias) { b0 = bias[cb]; b1 = bias[cb + 1]; }
            float v0 = acc[mt][nt][0] + b0;
            float v1 = acc[mt][nt][1] + b1;
            float v2 = acc[mt][nt][2] + b0;
            float v3 = acc[mt][nt][3] + b1;
            v0 = v0 >= 0.f ? v0 : alv * v0;
            v1 = v1 >= 0.f ? v1 : alv * v1;
            v2 = v2 >= 0.f ? v2 : alv * v2;
            v3 = v3 >= 0.f ? v3 : alv * v3;
            if (MODE == 1) {
                *(__half2*)&Yh[(size_t)r0 * DD + cb] =
                    __halves2half2(__float2half_rn(v0), __float2half_rn(v1));
                *(__half2*)&Yh[(size_t)(r0 + 8) * DD + cb] =
                    __halves2half2(__float2half_rn(v2), __float2half_rn(v3));
            } else {
                float w0 = Wo[cb], w1 = Wo[cb + 1];
                p0 = fmaf(v0, w0, fmaf(v1, w1, p0));
                p1 = fmaf(v2, w0, fmaf(v3, w1, p1));
            }
        }
        if (MODE == 2) {
            p0 += __shfl_xor_sync(0xffffffffu, p0, 1);
            p0 += __shfl_xor_sync(0xffffffffu, p0, 2);
            p1 += __shfl_xor_sync(0xffffffffu, p1, 1);
            p1 += __shfl_xor_sync(0xffffffffu, p1, 2);
            if (t4 == 0) {
                atomicAdd(&g_angles[r0],     p0);
                atomicAdd(&g_angles[r0 + 8], p1);
            }
        }
    }
}

// ---------------- edge passes -------------------------------------------
// adjacency build (side stream; only touches g_A + eidx)
__global__ void edge_adj_kernel(const int* __restrict__ ei, int E)
{
    int t = blockIdx.x * blockDim.x + threadIdx.x;
    if (t >= E) return;
    int s = ei[t];
    int d = ei[E + t];
    atomicOr(&g_A[s * NW + (d >> 5)], 1u << (d & 31));
}

// hop-1 raw segment sum (needs angles); angles_full(d) = g_angles[d] + bo
__global__ void edge_sum_kernel(const int* __restrict__ ei, int E,
                                const float* __restrict__ bo)
{
    int t = blockIdx.x * blockDim.x + threadIdx.x;
    if (t >= E) return;
    int s = ei[t];
    int d = ei[E + t];
    atomicAdd(&g_acc[s], g_angles[d] + bo[0]);   // duplicates count
}

__global__ void a1_kernel(const float* __restrict__ bo)
{
    int i = blockIdx.x * blockDim.x + threadIdx.x;
    if (i < NN) g_a1[i] = (g_angles[i] + bo[0]) + 0.25f * g_acc[i];  // (0.5)^2
}

// ======================================================================
//  Bit-matrix power kernels (side stream): prefix-sum neighbor
//  extraction + 8-way unrolled row-OR.  dst = bool(nbr-OR of nbrmat).
// ======================================================================
__global__ __launch_bounds__(128) void hop_bits_kernel(
    const unsigned* __restrict__ nbrmat, unsigned* __restrict__ dstmat)
{
    const int i = blockIdx.x;
    const int t = threadIdx.x;  // 0..127

    __shared__ unsigned short s_nbr[4096];
    __shared__ int s_wtot[4];
    __shared__ int s_deg;

    // --- extract row i's 1-hop neighbor list (deterministic order) ---
    unsigned mybits = g_A[i * NW + t];
    int cnt = __popc(mybits);
    int incl = cnt;
#pragma unroll
    for (int o = 1; o < 32; o <<= 1) {
        int v = __shfl_up_sync(0xffffffffu, incl, o);
        if ((t & 31) >= o) incl += v;
    }
    if ((t & 31) == 31) s_wtot[t >> 5] = incl;
    __syncthreads();
    int base = incl - cnt;
#pragma unroll
    for (int w = 0; w < 4; ++w)
        if (w < (t >> 5)) base += s_wtot[w];
    int pos = base;
    unsigned bb = mybits;
    while (bb) {
        int b = __ffs(bb) - 1;
        bb &= bb - 1;
        s_nbr[pos++] = (unsigned short)(t * 32 + b);
    }
    if (t == 127) s_deg = base + cnt;
    __syncthreads();
    const int deg = s_deg;

    // --- OR neighbor rows (word t), 8-way ILP ---
    unsigned accw = 0u;
    int j = 0;
    for (; j + 8 <= deg; j += 8) {
        unsigned v0 = nbrmat[s_nbr[j]     * NW + t];
        unsigned v1 = nbrmat[s_nbr[j + 1] * NW + t];
        unsigned v2 = nbrmat[s_nbr[j + 2] * NW + t];
        unsigned v3 = nbrmat[s_nbr[j + 3] * NW + t];
        unsigned v4 = nbrmat[s_nbr[j + 4] * NW + t];
        unsigned v5 = nbrmat[s_nbr[j + 5] * NW + t];
        unsigned v6 = nbrmat[s_nbr[j + 6] * NW + t];
        unsigned v7 = nbrmat[s_nbr[j + 7] * NW + t];
        accw |= ((v0 | v1) | (v2 | v3)) | ((v4 | v5) | (v6 | v7));
    }
    for (; j < deg; ++j) accw |= nbrmat[s_nbr[j] * NW + t];

    dstmat[i * NW + t] = accw;
}

// ======================================================================
//  Gather kernels (critical path, cheap): dst[i] = vec[i] +
//  scale * sum_{j in bits(mat row i)} vec[j].
// ======================================================================
__global__ __launch_bounds__(128) void gather_kernel(
    const unsigned* __restrict__ mat, const float* __restrict__ vec,
    float scale, float* __restrict__ dst)
{
    const int i = blockIdx.x;
    const int t = threadIdx.x;

    __shared__ unsigned swords[NW];
    __shared__ float red[NW];

    swords[t] = mat[i * NW + t];
    __syncthreads();

    float p = 0.f;
#pragma unroll 4
    for (int k = 0; k < 32; ++k) {
        int idx = k * 128 + t;
        unsigned wrd = swords[idx >> 5];
        p += vec[idx] * (float)((wrd >> (idx & 31)) & 1u);
    }
    red[t] = p;
    __syncthreads();
#pragma unroll
    for (int s = 64; s; s >>= 1) {
        if (t < s) red[t] += red[t + s];
        __syncthreads();
    }
    if (t == 0) dst[i] = vec[i] + scale * red[0];
}

// ---------------------------- launch ------------------------------------
extern "C" void kernel_launch(void* const* d_in, const int* in_sizes, int n_in,
                              void* d_out, int out_size)
{
    const float* coeffs = (const float*)d_in[0];
    const int*   eidx   = (const int*)  d_in[1];
    const float* W0     = (const float*)d_in[2];
    const float* b0     = (const float*)d_in[3];
    const float* a0     = (const float*)d_in[4];
    const float* W1     = (const float*)d_in[5];
    const float* a1p    = (const float*)d_in[6];
    const float* W2     = (const float*)d_in[7];
    const float* a2p    = (const float*)d_in[8];
    const float* Wo     = (const float*)d_in[9];
    const float* bo     = (const float*)d_in[10];
    float* out = (float*)d_out;

    const int E = in_sizes[1] / 2;

    __half *p_xh, *p_yh, *p_wh, *p_wl;
    float *p_a1, *p_a2;
    unsigned *p_A, *p_A2, *p_A3;
    cudaGetSymbolAddress((void**)&p_xh, g_xh);
    cudaGetSymbolAddress((void**)&p_yh, g_yh);
    cudaGetSymbolAddress((void**)&p_wh, g_wh);
    cudaGetSymbolAddress((void**)&p_wl, g_wl);
    cudaGetSymbolAddress((void**)&p_a1, g_a1);
    cudaGetSymbolAddress((void**)&p_a2, g_a2);
    cudaGetSymbolAddress((void**)&p_A,  g_A);
    cudaGetSymbolAddress((void**)&p_A2, g_A2);
    cudaGetSymbolAddress((void**)&p_A3, g_A3);

    cudaFuncSetAttribute(tc_gemm<1>, cudaFuncAttributeMaxDynamicSharedMemorySize, GEMM_SMEM);
    cudaFuncSetAttribute(tc_gemm<2>, cudaFuncAttributeMaxDynamicSharedMemorySize, GEMM_SMEM);

    // one-time side stream + events (same graph shape every call)
    static cudaStream_t s2 = nullptr;
    static cudaEvent_t evFork = nullptr, evJoin = nullptr;
    if (!s2) {
        cudaStreamCreateWithFlags(&s2, cudaStreamNonBlocking);
        cudaEventCreateWithFlags(&evFork, cudaEventDisableTiming);
        cudaEventCreateWithFlags(&evJoin, cudaEventDisableTiming);
    }

    // ---- fork: side stream computes adjacency powers (A, A2, A3) ----
    cudaEventRecord(evFork, 0);
    cudaStreamWaitEvent(s2, evFork, 0);
    zeroA_kernel<<<512, 256, 0, s2>>>();
    edge_adj_kernel<<<(E + 255) / 256, 256, 0, s2>>>(eidx, E);
    hop_bits_kernel<<<NN, 128, 0, s2>>>(p_A,  p_A2);   // A2 = bool(A@A)
    hop_bits_kernel<<<NN, 128, 0, s2>>>(p_A2, p_A3);   // A3 = bool(A@A2)
    cudaEventRecord(evJoin, s2);

    // ---- main stream: splits + MLP chain ----
    splitx_kernel<<<(NN * DD / 4 + 255) / 256, 256>>>(coeffs, p_xh, NN * DD);
    splitw_kernel<<<(3 * DD * DD / 4 + 255) / 256, 256>>>(W0, W1, W2, p_wh, p_wl);

    dim3 ggrid(DD / BN, NN / BM);   // (4, 32) = 128 CTAs
    tc_gemm<1><<<ggrid, NT, GEMM_SMEM>>>(p_xh, p_wh + 0 * DD * DD, p_wl + 0 * DD * DD,
                                         b0,      a0,  nullptr, p_yh);
    tc_gemm<1><<<ggrid, NT, GEMM_SMEM>>>(p_yh, p_wh + 1 * DD * DD, p_wl + 1 * DD * DD,
                                         nullptr, a1p, nullptr, p_xh);
    tc_gemm<2><<<ggrid, NT, GEMM_SMEM>>>(p_xh, p_wh + 2 * DD * DD, p_wl + 2 * DD * DD,
                                         nullptr, a2p, Wo, nullptr);

    // ---- hop-1 (needs angles) ----
    edge_sum_kernel<<<(E + 255) / 256, 256>>>(eidx, E, bo);
    a1_kernel<<<(NN + 255) / 256, 256>>>(bo);

    // ---- join: gathers need A2/A3 bits ----
    cudaStreamWaitEvent(0, evJoin, 0);
    gather_kernel<<<NN, 128>>>(p_A2, p_a1, 1.0f / 9.0f,  p_a2);
    gather_kernel<<<NN, 128>>>(p_A3, p_a2, 1.0f / 16.0f, out);
}